// round 7
// baseline (speedup 1.0000x reference)
#include <cuda_runtime.h>
#include <cstdint>

#define TOK 4096   // B*S tokens
#define HD  1024
#define NE  8
#define FF  4096
#define TOPK 2

// ---------------- scratch (device globals) ----------------
__device__ int   g_counts[NE];
__device__ int   g_tok[NE][TOK];
__device__ int   g_sel_e[TOK * TOPK];
__device__ int   g_sel_s[TOK * TOPK];
__device__ float g_sel_w[TOK * TOPK];
__device__ float g_h[(size_t)TOK * TOPK * FF];   // tf32-rounded activations (unpermuted)
__device__ float g_y[(size_t)TOK * TOPK * HD];
// tf32-rounded, k-permuted operands. perm within 32-block: k' = (k%4)*8 + k/4
__device__ float g_xt[(size_t)TOK * HD];          // [t][k']
__device__ float g_w1t[(size_t)NE * HD * FF];     // [e][n=FF][k'=HD]  (transposed)
__device__ float g_w3t[(size_t)NE * HD * FF];
__device__ float g_w2t[(size_t)NE * FF * HD];     // [e][n=HD][k'=FF]

// ---------------- helpers ----------------
__device__ __forceinline__ uint32_t f2tf(float f) {
    uint32_t u; asm("cvt.rna.tf32.f32 %0, %1;" : "=r"(u) : "f"(f)); return u;
}
__device__ __forceinline__ uint32_t smem_u32(const void* p) {
    uint32_t a;
    asm("{ .reg .u64 t; cvta.to.shared.u64 t, %1; cvt.u32.u64 %0, t; }" : "=r"(a) : "l"(p));
    return a;
}
__device__ __forceinline__ void mma8(float* d, const uint32_t* a, const uint32_t* b) {
    asm volatile("mma.sync.aligned.m16n8k8.row.col.f32.tf32.tf32.f32 "
        "{%0,%1,%2,%3}, {%4,%5,%6,%7}, {%8,%9}, {%0,%1,%2,%3};"
        : "+f"(d[0]), "+f"(d[1]), "+f"(d[2]), "+f"(d[3])
        : "r"(a[0]), "r"(a[1]), "r"(a[2]), "r"(a[3]), "r"(b[0]), "r"(b[1]));
}
#define CP16(dst32, src) \
    asm volatile("cp.async.cg.shared.global [%0], [%1], 16;" :: "r"(dst32), "l"(src) : "memory")
#define CP_COMMIT() asm volatile("cp.async.commit_group;" ::: "memory")
#define CP_WAIT0()  asm volatile("cp.async.wait_group 0;" ::: "memory")
#define CP_WAIT1()  asm volatile("cp.async.wait_group 1;" ::: "memory")
#define LDS128(v, addr) \
    asm volatile("ld.shared.v4.b32 {%0,%1,%2,%3}, [%4];" \
        : "=r"((v).x), "=r"((v).y), "=r"((v).z), "=r"((v).w) : "r"(addr))

// ---------------- prep: x -> rounded + k-permuted; also zero counters ----------------
__global__ void prep_x_kernel(const float4* __restrict__ x) {
    __shared__ float buf[HD];
    const int t = blockIdx.x, tid = threadIdx.x;
    if (t == 0 && tid < NE) g_counts[tid] = 0;
    float4 v = x[(size_t)t * (HD / 4) + tid];
    const float vv[4] = {v.x, v.y, v.z, v.w};
    #pragma unroll
    for (int j = 0; j < 4; j++) {
        int k = tid * 4 + j;
        int p = (k & ~31) | ((k & 3) << 3) | ((k & 31) >> 2);
        buf[p] = __uint_as_float(f2tf(vv[j]));
    }
    __syncthreads();
    ((float4*)g_xt)[(size_t)t * (HD / 4) + tid] = ((const float4*)buf)[tid];
}

// ---------------- prep: W [e][K][N] -> rounded, transposed, k-permuted [e][N][K'] ----------------
__device__ __forceinline__ void prep_w_tile(const float* __restrict__ src,
                                            float* __restrict__ dst,
                                            int K, int N, int e, int k0, int n0) {
    __shared__ float tile[32][33];
    const int tid = threadIdx.x;
    const int r = tid >> 3, cq = (tid & 7) * 4;
    const float4 v = *(const float4*)(src + (size_t)e * K * N + (size_t)(k0 + r) * N + n0 + cq);
    tile[r][cq + 0] = __uint_as_float(f2tf(v.x));
    tile[r][cq + 1] = __uint_as_float(f2tf(v.y));
    tile[r][cq + 2] = __uint_as_float(f2tf(v.z));
    tile[r][cq + 3] = __uint_as_float(f2tf(v.w));
    __syncthreads();
    float4 o;
    float* ow = (float*)&o;
    #pragma unroll
    for (int j = 0; j < 4; j++) {
        int q = cq + j;                       // permuted word index within 32-block
        ow[j] = tile[(q & 7) * 4 + (q >> 3)][r];  // inverse perm: k = (q%8)*4 + q/8
    }
    *(float4*)(dst + (size_t)e * (size_t)N * K + (size_t)(n0 + r) * K + k0 + cq) = o;
}

__global__ void prep_w13_kernel(const float* __restrict__ W1, const float* __restrict__ W3) {
    const int z = blockIdx.z;
    prep_w_tile((z < NE) ? W1 : W3, (z < NE) ? g_w1t : g_w3t,
                HD, FF, z & 7, blockIdx.y * 32, blockIdx.x * 32);
}
__global__ void prep_w2_kernel(const float* __restrict__ W2) {
    prep_w_tile(W2, g_w2t, FF, HD, blockIdx.z, blockIdx.y * 32, blockIdx.x * 32);
}

// ---------------- routing (uses original x) ----------------
__global__ void routing_kernel(const float* __restrict__ x,
                               const float* __restrict__ Wg,
                               const float* __restrict__ bg) {
    const int t = blockIdx.x, tid = threadIdx.x, wid = tid >> 5, lid = tid & 31;
    __shared__ float s_logit[NE];
    const float* xt = x + (size_t)t * HD;
    float acc = 0.f;
    for (int h = lid; h < HD; h += 32) acc += xt[h] * Wg[h * NE + wid];
    #pragma unroll
    for (int o = 16; o > 0; o >>= 1) acc += __shfl_down_sync(0xFFFFFFFFu, acc, o);
    if (lid == 0) s_logit[wid] = acc + bg[wid];
    __syncthreads();
    if (tid == 0) {
        float l[NE];
        #pragma unroll
        for (int e = 0; e < NE; e++) l[e] = s_logit[e];
        int i0 = 0;
        #pragma unroll
        for (int e = 1; e < NE; e++) if (l[e] > l[i0]) i0 = e;
        int i1 = (i0 == 0) ? 1 : 0;
        #pragma unroll
        for (int e = 0; e < NE; e++) if (e != i0 && l[e] > l[i1]) i1 = e;
        float w1 = __expf(l[i1] - l[i0]);
        float inv = 1.f / (1.f + w1);
        int s0 = atomicAdd(&g_counts[i0], 1);
        int s1 = atomicAdd(&g_counts[i1], 1);
        g_tok[i0][s0] = t;  g_tok[i1][s1] = t;
        g_sel_e[t*2+0] = i0; g_sel_s[t*2+0] = s0; g_sel_w[t*2+0] = inv;
        g_sel_e[t*2+1] = i1; g_sel_s[t*2+1] = s1; g_sel_w[t*2+1] = w1 * inv;
    }
}

// ======================= GEMM1 =======================
// CTA 128M x 64N fused (W1,W3), BK=32, 3-stage cp.async, 2 CTA/SM.
// A smem [128 m][36 pad] (k'-permuted content), B smem [64 n][36 pad].
// Fragments: one LDS.128 per thread covers k16 per row.
#define G1_A_OFF  512
#define G1_B1_OFF 55808
#define G1_B3_OFF 83456
#define G1_SMEM   111104
#define G1_A_STG  18432
#define G1_B_STG  9216

__device__ __forceinline__ void g1_load_stage(uint32_t sb, int s, int c,
                                              const int* toks,
                                              const float* __restrict__ W1t,
                                              const float* __restrict__ W3t,
                                              int n0, int tid) {
    const int k0 = c * 32;
    const uint32_t aB = sb + G1_A_OFF + s * G1_A_STG;
    #pragma unroll
    for (int q = 0; q < 4; q++) {
        int id = q * 256 + tid, row = id >> 3, c4 = id & 7;
        CP16(aB + row * 144 + c4 * 16, g_xt + (size_t)toks[row] * HD + k0 + c4 * 4);
    }
    const uint32_t b1B = sb + G1_B1_OFF + s * G1_B_STG;
    const uint32_t b3B = sb + G1_B3_OFF + s * G1_B_STG;
    #pragma unroll
    for (int q = 0; q < 2; q++) {
        int id = q * 256 + tid, row = id >> 3, c4 = id & 7;     // 64 n-rows x 8 granules
        size_t off = (size_t)(n0 + row) * HD + k0 + c4 * 4;
        CP16(b1B + row * 144 + c4 * 16, W1t + off);
        CP16(b3B + row * 144 + c4 * 16, W3t + off);
    }
    CP_COMMIT();
}

__global__ __launch_bounds__(256, 2) void gemm1_mma() {
    const int e = blockIdx.z;
    int n = 0, base = 0;
    #pragma unroll
    for (int i = 0; i < NE; i++) {
        int ci = g_counts[i];
        if (i < e) base += ci;
        if (i == e) n = ci;
    }
    const int m0 = blockIdx.y * 128;
    if (m0 >= n) return;
    const int n0 = blockIdx.x * 64;

    extern __shared__ char dynsmem[];
    const uint32_t sb = smem_u32(dynsmem);
    int* toks = (int*)dynsmem;

    const int tid = threadIdx.x, wid = tid >> 5, lane = tid & 31;
    const int g = lane >> 2, tig = lane & 3;
    const int wm = wid >> 1, wn = wid & 1;

    if (tid < 128) { int r = m0 + tid; toks[tid] = g_tok[e][r < n ? r : n - 1]; }
    __syncthreads();

    const float* __restrict__ W1t = g_w1t + (size_t)e * HD * FF;
    const float* __restrict__ W3t = g_w3t + (size_t)e * HD * FF;

    float cg[2][4][4] = {};
    float cu[2][4][4] = {};

    g1_load_stage(sb, 0, 0, toks, W1t, W3t, n0, tid);
    g1_load_stage(sb, 1, 1, toks, W1t, W3t, n0, tid);

    // per-thread fragment byte offsets (within a stage)
    const uint32_t aoff  = (uint32_t)((wm * 32 + g) * 144 + tig * 32);
    const uint32_t boff  = (uint32_t)((wn * 32 + g) * 144 + tig * 32);

    const int NC = HD / 32;
    for (int c = 0; c < NC; c++) {
        if (c + 1 < NC) { CP_WAIT1(); } else { CP_WAIT0(); }
        __syncthreads();
        if (c + 2 < NC)
            g1_load_stage(sb, (c + 2) % 3, c + 2, toks, W1t, W3t, n0, tid);

        const int s = c % 3;
        const uint32_t aB  = sb + G1_A_OFF  + s * G1_A_STG + aoff;
        const uint32_t b1B = sb + G1_B1_OFF + s * G1_B_STG + boff;
        const uint32_t b3B = sb + G1_B3_OFF + s * G1_B_STG + boff;

        #pragma unroll
        for (int h = 0; h < 2; h++) {
            uint4 Ar[4], B1r[4], B3r[4];
            #pragma unroll
            for (int i = 0; i < 4; i++)
                LDS128(Ar[i], aB + i * (8 * 144) + h * 16);
            #pragma unroll
            for (int nt = 0; nt < 4; nt++) {
                LDS128(B1r[nt], b1B + nt * (8 * 144) + h * 16);
                LDS128(B3r[nt], b3B + nt * (8 * 144) + h * 16);
            }
            #pragma unroll
            for (int kp = 0; kp < 2; kp++) {
                uint32_t a[2][4];
                #pragma unroll
                for (int mt = 0; mt < 2; mt++) {
                    const uint32_t* lo = (const uint32_t*)&Ar[2 * mt];
                    const uint32_t* hi = (const uint32_t*)&Ar[2 * mt + 1];
                    a[mt][0] = lo[2 * kp];     a[mt][1] = hi[2 * kp];
                    a[mt][2] = lo[2 * kp + 1]; a[mt][3] = hi[2 * kp + 1];
                }
                #pragma unroll
                for (int nt = 0; nt < 4; nt++) {
                    const uint32_t* p1 = (const uint32_t*)&B1r[nt];
                    const uint32_t* p3 = (const uint32_t*)&B3r[nt];
                    uint32_t b1[2] = { p1[2 * kp], p1[2 * kp + 1] };
                    uint32_t b3[2] = { p3[2 * kp], p3[2 * kp + 1] };
                    #pragma unroll
                    for (int mt = 0; mt < 2; mt++) {
                        mma8(cg[mt][nt], a[mt], b1);
                        mma8(cu[mt][nt], a[mt], b3);
                    }
                }
            }
        }
    }

    // epilogue: h = silu(g) * u, rounded to tf32 for gemm2 (g_h unpermuted)
    #pragma unroll
    for (int mt = 0; mt < 2; mt++) {
        #pragma unroll
        for (int half = 0; half < 2; half++) {
            const int r = m0 + wm * 32 + mt * 16 + g + half * 8;
            if (r >= n) continue;
            float* hp = g_h + (size_t)(base + r) * FF + n0 + wn * 32 + 2 * tig;
            #pragma unroll
            for (int nt = 0; nt < 4; nt++) {
                float g0 = cg[mt][nt][half * 2 + 0], g1 = cg[mt][nt][half * 2 + 1];
                float u0 = cu[mt][nt][half * 2 + 0], u1 = cu[mt][nt][half * 2 + 1];
                float2 o;
                o.x = __uint_as_float(f2tf((g0 / (1.f + __expf(-g0))) * u0));
                o.y = __uint_as_float(f2tf((g1 / (1.f + __expf(-g1))) * u1));
                *(float2*)(hp + nt * 8) = o;
            }
        }
    }
}

// ======================= GEMM2 =======================
// CTA 128M x 128N, BK=32, 3-stage. A [128 m][36] from g_h (unpermuted, scalar frags);
// B [128 n][36] from g_w2t (k'-permuted, vector frags).
#define G2_B_OFF 55296
#define G2_SMEM  110592
#define G2_A_STG 18432
#define G2_B_STG 18432

__device__ __forceinline__ void g2_load_stage(uint32_t sb, int s, int c,
                                              const float* __restrict__ W2t,
                                              int base, int m0, int n, int n0, int tid) {
    const int k0 = c * 32;
    const uint32_t aB = sb + s * G2_A_STG;
    #pragma unroll
    for (int q = 0; q < 4; q++) {
        int id = q * 256 + tid, row = id >> 3, c4 = id & 7;
        int rg = m0 + row; if (rg >= n) rg = n - 1;
        CP16(aB + row * 144 + c4 * 16, g_h + (size_t)(base + rg) * FF + k0 + c4 * 4);
    }
    const uint32_t bB = sb + G2_B_OFF + s * G2_B_STG;
    #pragma unroll
    for (int q = 0; q < 4; q++) {
        int id = q * 256 + tid, row = id >> 3, c4 = id & 7;     // 128 n-rows x 8 granules
        CP16(bB + row * 144 + c4 * 16, W2t + (size_t)(n0 + row) * FF + k0 + c4 * 4);
    }
    CP_COMMIT();
}

__global__ __launch_bounds__(256, 2) void gemm2_mma() {
    const int e = blockIdx.z;
    int n = 0, base = 0;
    #pragma unroll
    for (int i = 0; i < NE; i++) {
        int ci = g_counts[i];
        if (i < e) base += ci;
        if (i == e) n = ci;
    }
    const int m0 = blockIdx.y * 128;
    if (m0 >= n) return;
    const int n0 = blockIdx.x * 128;

    extern __shared__ char dynsmem[];
    const uint32_t sb = smem_u32(dynsmem);
    const uint32_t* As = (const uint32_t*)dynsmem;

    const int tid = threadIdx.x, wid = tid >> 5, lane = tid & 31;
    const int g = lane >> 2, tig = lane & 3;
    const int wm = wid >> 1, wn = wid & 1;

    const float* __restrict__ W2t = g_w2t + (size_t)e * FF * HD;

    float cacc[2][8][4] = {};

    g2_load_stage(sb, 0, 0, W2t, base, m0, n, n0, tid);
    g2_load_stage(sb, 1, 1, W2t, base, m0, n, n0, tid);

    const uint32_t boff = (uint32_t)((wn * 64 + g) * 144 + tig * 32);

    const int NC = FF / 32;
    for (int c = 0; c < NC; c++) {
        if (c + 1 < NC) { CP_WAIT1(); } else { CP_WAIT0(); }
        __syncthreads();
        if (c + 2 < NC)
            g2_load_stage(sb, (c + 2) % 3, c + 2, W2t, base, m0, n, n0, tid);

        const int s = c % 3;
        const uint32_t* Ap = As + s * 4608;           // 128*36 words
        const uint32_t bB  = sb + G2_B_OFF + s * G2_B_STG + boff;

        #pragma unroll
        for (int h = 0; h < 2; h++) {
            uint4 Br[8];
            #pragma unroll
            for (int nt = 0; nt < 8; nt++)
                LDS128(Br[nt], bB + nt * (8 * 144) + h * 16);
            #pragma unroll
            for (int kp = 0; kp < 2; kp++) {
                const int ks = h * 2 + kp;
                const int kk = ks * 8;
                uint32_t a[2][4];
                #pragma unroll
                for (int mt = 0; mt < 2; mt++) {
                    const int rb = wm * 32 + mt * 16;
                    a[mt][0] = Ap[(rb + g) * 36 + kk + tig];
                    a[mt][1] = Ap[(rb + g + 8) * 36 + kk + tig];
                    a[mt][2] = Ap[(rb + g) * 36 + kk + tig + 4];
                    a[mt][3] = Ap[(rb + g + 8) * 36 + kk + tig + 4];
                }
                #pragma unroll
                for (int nt = 0; nt < 8; nt++) {
                    const uint32_t* pw = (const uint32_t*)&Br[nt];
                    uint32_t b[2] = { pw[2 * kp], pw[2 * kp + 1] };
                    #pragma unroll
                    for (int mt = 0; mt < 2; mt++) mma8(cacc[mt][nt], a[mt], b);
                }
            }
        }
    }

    #pragma unroll
    for (int mt = 0; mt < 2; mt++) {
        #pragma unroll
        for (int half = 0; half < 2; half++) {
            const int r = m0 + wm * 32 + mt * 16 + g + half * 8;
            if (r >= n) continue;
            float* yp = g_y + (size_t)(base + r) * HD + n0 + wn * 64 + 2 * tig;
            #pragma unroll
            for (int nt = 0; nt < 8; nt++) {
                float2 o;
                o.x = cacc[mt][nt][half * 2 + 0];
                o.y = cacc[mt][nt][half * 2 + 1];
                *(float2*)(yp + nt * 8) = o;
            }
        }
    }
}

// ---------------- combine ----------------
__global__ void combine_kernel(float* __restrict__ out) {
    __shared__ int sbase[NE];
    if (threadIdx.x == 0) {
        int b = 0;
        #pragma unroll
        for (int e = 0; e < NE; e++) { sbase[e] = b; b += g_counts[e]; }
    }
    __syncthreads();
    const int idx = blockIdx.x * blockDim.x + threadIdx.x;
    const int t = idx / (HD / 4);
    const int c4 = idx % (HD / 4);
    float4 acc = make_float4(0.f, 0.f, 0.f, 0.f);
    #pragma unroll
    for (int k = 0; k < TOPK; k++) {
        int e = g_sel_e[t * 2 + k];
        int s = g_sel_s[t * 2 + k];
        float w = g_sel_w[t * 2 + k];
        const float4 v = *(const float4*)(g_y + (size_t)(sbase[e] + s) * HD + c4 * 4);
        acc.x += w * v.x; acc.y += w * v.y; acc.z += w * v.z; acc.w += w * v.w;
    }
    *(float4*)(out + (size_t)t * HD + c4 * 4) = acc;
}

// ---------------- launcher ----------------
extern "C" void kernel_launch(void* const* d_in, const int* in_sizes, int n_in,
                              void* d_out, int out_size) {
    const float* x  = (const float*)d_in[0];
    const float* Wg = (const float*)d_in[1];
    const float* bg = (const float*)d_in[2];
    const float* W1 = (const float*)d_in[3];
    const float* W3 = (const float*)d_in[4];
    const float* W2 = (const float*)d_in[5];
    float* out = (float*)d_out;

    cudaFuncSetAttribute(gemm1_mma, cudaFuncAttributeMaxDynamicSharedMemorySize, G1_SMEM);
    cudaFuncSetAttribute(gemm2_mma, cudaFuncAttributeMaxDynamicSharedMemorySize, G2_SMEM);

    // launch index 3 = gemm1 (ncu capture slot)
    prep_x_kernel<<<TOK, 256>>>((const float4*)x);                       // 0 (also zeros counters)
    routing_kernel<<<TOK, 256>>>(x, Wg, bg);                             // 1
    prep_w13_kernel<<<dim3(FF / 32, HD / 32, 2 * NE), 256>>>(W1, W3);    // 2
    gemm1_mma<<<dim3(FF / 64, TOK / 128, NE), 256, G1_SMEM>>>();         // 3
    prep_w2_kernel<<<dim3(HD / 32, FF / 32, NE), 256>>>(W2);             // 4
    gemm2_mma<<<dim3(HD / 128, TOK / 128, NE), 256, G2_SMEM>>>();        // 5
    combine_kernel<<<(TOK * (HD / 4)) / 256, 256>>>(out);                // 6
}

// round 8
// speedup vs baseline: 2.0675x; 2.0675x over previous
#include <cuda_runtime.h>
#include <cuda_fp16.h>
#include <cstdint>

#define TOK 4096   // B*S tokens
#define HD  1024
#define NE  8
#define FF  4096
#define TOPK 2

// ---------------- scratch (device globals) ----------------
__device__ int   g_counts[NE];
__device__ int   g_tok[NE][TOK];
__device__ int   g_sel_e[TOK * TOPK];
__device__ int   g_sel_s[TOK * TOPK];
__device__ float g_sel_w[TOK * TOPK];
__device__ float g_y[(size_t)TOK * TOPK * HD];
// fp16 operand copies (natural layouts, no transpose)
__device__ __align__(16) __half g_xh[(size_t)TOK * HD];          // [t][k]
__device__ __align__(16) __half g_w1h[(size_t)NE * HD * FF];     // [e][k][n]
__device__ __align__(16) __half g_w3h[(size_t)NE * HD * FF];
__device__ __align__(16) __half g_w2h[(size_t)NE * FF * HD];     // [e][k][n]
__device__ __align__(16) __half g_hh[(size_t)TOK * TOPK * FF];   // SwiGLU out, fp16

// ---------------- helpers ----------------
__device__ __forceinline__ uint32_t smem_u32(const void* p) {
    uint32_t a;
    asm("{ .reg .u64 t; cvta.to.shared.u64 t, %1; cvt.u32.u64 %0, t; }" : "=r"(a) : "l"(p));
    return a;
}
__device__ __forceinline__ void mma16(float* d, const uint32_t* a, const uint32_t* b) {
    asm volatile("mma.sync.aligned.m16n8k16.row.col.f32.f16.f16.f32 "
        "{%0,%1,%2,%3}, {%4,%5,%6,%7}, {%8,%9}, {%0,%1,%2,%3};"
        : "+f"(d[0]), "+f"(d[1]), "+f"(d[2]), "+f"(d[3])
        : "r"(a[0]), "r"(a[1]), "r"(a[2]), "r"(a[3]), "r"(b[0]), "r"(b[1]));
}
__device__ __forceinline__ void ldmx4(uint32_t* r, uint32_t addr) {
    asm volatile("ldmatrix.sync.aligned.m8n8.x4.shared.b16 {%0,%1,%2,%3}, [%4];"
        : "=r"(r[0]), "=r"(r[1]), "=r"(r[2]), "=r"(r[3]) : "r"(addr));
}
__device__ __forceinline__ void ldmx4t(uint32_t* r, uint32_t addr) {
    asm volatile("ldmatrix.sync.aligned.m8n8.x4.trans.shared.b16 {%0,%1,%2,%3}, [%4];"
        : "=r"(r[0]), "=r"(r[1]), "=r"(r[2]), "=r"(r[3]) : "r"(addr));
}
#define CP16(dst32, src) \
    asm volatile("cp.async.cg.shared.global [%0], [%1], 16;" :: "r"(dst32), "l"(src) : "memory")
#define CP_COMMIT() asm volatile("cp.async.commit_group;" ::: "memory")
#define CP_WAIT0()  asm volatile("cp.async.wait_group 0;" ::: "memory")
#define CP_WAIT1()  asm volatile("cp.async.wait_group 1;" ::: "memory")
__device__ __forceinline__ uint32_t h2u(__half2 h) { return *reinterpret_cast<uint32_t*>(&h); }

// ---------------- prep: fp32 -> fp16 converts ----------------
__global__ void cvt_x_kernel(const float4* __restrict__ x) {
    int i = blockIdx.x * blockDim.x + threadIdx.x;
    if (blockIdx.x == 0 && threadIdx.x < NE) g_counts[threadIdx.x] = 0;
    if (i < TOK * HD / 4) {
        float4 v = x[i];
        uint2 o;
        o.x = h2u(__floats2half2_rn(v.x, v.y));
        o.y = h2u(__floats2half2_rn(v.z, v.w));
        ((uint2*)g_xh)[i] = o;
    }
}
__global__ void cvt_w13_kernel(const float4* __restrict__ W1, const float4* __restrict__ W3) {
    const int n4 = NE * HD * FF / 4;
    int i = blockIdx.x * blockDim.x + threadIdx.x;
    const float4* s = (i < n4) ? W1 : W3;
    uint2* d = (i < n4) ? (uint2*)g_w1h : (uint2*)g_w3h;
    int j = (i < n4) ? i : i - n4;
    float4 v = s[j];
    uint2 o;
    o.x = h2u(__floats2half2_rn(v.x, v.y));
    o.y = h2u(__floats2half2_rn(v.z, v.w));
    d[j] = o;
}
__global__ void cvt_w2_kernel(const float4* __restrict__ W2) {
    int i = blockIdx.x * blockDim.x + threadIdx.x;
    float4 v = W2[i];
    uint2 o;
    o.x = h2u(__floats2half2_rn(v.x, v.y));
    o.y = h2u(__floats2half2_rn(v.z, v.w));
    ((uint2*)g_w2h)[i] = o;
}

// ---------------- routing (fp32, unchanged) ----------------
__global__ void routing_kernel(const float* __restrict__ x,
                               const float* __restrict__ Wg,
                               const float* __restrict__ bg) {
    const int t = blockIdx.x, tid = threadIdx.x, wid = tid >> 5, lid = tid & 31;
    __shared__ float s_logit[NE];
    const float* xt = x + (size_t)t * HD;
    float acc = 0.f;
    for (int h = lid; h < HD; h += 32) acc += xt[h] * Wg[h * NE + wid];
    #pragma unroll
    for (int o = 16; o > 0; o >>= 1) acc += __shfl_down_sync(0xFFFFFFFFu, acc, o);
    if (lid == 0) s_logit[wid] = acc + bg[wid];
    __syncthreads();
    if (tid == 0) {
        float l[NE];
        #pragma unroll
        for (int e = 0; e < NE; e++) l[e] = s_logit[e];
        int i0 = 0;
        #pragma unroll
        for (int e = 1; e < NE; e++) if (l[e] > l[i0]) i0 = e;
        int i1 = (i0 == 0) ? 1 : 0;
        #pragma unroll
        for (int e = 0; e < NE; e++) if (e != i0 && l[e] > l[i1]) i1 = e;
        float w1 = __expf(l[i1] - l[i0]);
        float inv = 1.f / (1.f + w1);
        int s0 = atomicAdd(&g_counts[i0], 1);
        int s1 = atomicAdd(&g_counts[i1], 1);
        g_tok[i0][s0] = t;  g_tok[i1][s1] = t;
        g_sel_e[t*2+0] = i0; g_sel_s[t*2+0] = s0; g_sel_w[t*2+0] = inv;
        g_sel_e[t*2+1] = i1; g_sel_s[t*2+1] = s1; g_sel_w[t*2+1] = w1 * inv;
    }
}

// ======================= GEMM1 (fp16) =======================
// CTA 128M x 64N fused (W1,W3), BK=32, 3-stage cp.async, 2 CTA/SM.
// A smem: [128 m][32 k halves], row stride 80B (ldmatrix banks 20r mod 32 — CF).
// B smem: [32 k][64 n halves], row stride 144B (ldmatrix.trans banks 4r — CF).
#define G1_A_OFF  512
#define G1_A_STG  10240
#define G1_B1_OFF (512 + 3 * 10240)          /* 31232 */
#define G1_B_STG  4608
#define G1_B3_OFF (31232 + 3 * 4608)         /* 45056 */
#define G1_SMEM   (45056 + 3 * 4608)         /* 58880 */

__device__ __forceinline__ void g1_load_stage(uint32_t sb, int s, int c,
                                              const int* toks,
                                              const __half* __restrict__ W1h,
                                              const __half* __restrict__ W3h,
                                              int n0, int tid) {
    const int k0 = c * 32;
    const uint32_t aB = sb + G1_A_OFF + s * G1_A_STG;
    #pragma unroll
    for (int q = 0; q < 2; q++) {               // 128 rows x 4 granules, 2/thread
        int id = q * 256 + tid, row = id >> 2, gq = id & 3;
        CP16(aB + row * 80 + gq * 16, g_xh + (size_t)toks[row] * HD + k0 + gq * 8);
    }
    {                                           // 32 rows x 8 granules, 1/thread each
        int row = tid >> 3, gq = tid & 7;
        size_t off = (size_t)(k0 + row) * FF + n0 + gq * 8;
        uint32_t so = row * 144 + gq * 16;
        CP16(sb + G1_B1_OFF + s * G1_B_STG + so, W1h + off);
        CP16(sb + G1_B3_OFF + s * G1_B_STG + so, W3h + off);
    }
    CP_COMMIT();
}

__global__ __launch_bounds__(256, 2) void gemm1_mma() {
    const int e = blockIdx.z;
    int n = 0, base = 0;
    #pragma unroll
    for (int i = 0; i < NE; i++) {
        int ci = g_counts[i];
        if (i < e) base += ci;
        if (i == e) n = ci;
    }
    const int m0 = blockIdx.y * 128;
    if (m0 >= n) return;
    const int n0 = blockIdx.x * 64;

    extern __shared__ char dynsmem[];
    const uint32_t sb = smem_u32(dynsmem);
    int* toks = (int*)dynsmem;

    const int tid = threadIdx.x, wid = tid >> 5, lane = tid & 31;
    const int g = lane >> 2, tig = lane & 3;
    const int wm = wid >> 1, wn = wid & 1;

    if (tid < 128) { int r = m0 + tid; toks[tid] = g_tok[e][r < n ? r : n - 1]; }
    __syncthreads();

    const __half* __restrict__ W1h = g_w1h + (size_t)e * HD * FF;
    const __half* __restrict__ W3h = g_w3h + (size_t)e * HD * FF;

    float cg[2][4][4] = {};
    float cu[2][4][4] = {};

    g1_load_stage(sb, 0, 0, toks, W1h, W3h, n0, tid);
    g1_load_stage(sb, 1, 1, toks, W1h, W3h, n0, tid);

    // per-lane ldmatrix base addresses (stage 0)
    const uint32_t aAddr  = sb + G1_A_OFF + (wm * 32 + (lane & 15)) * 80 + (lane >> 4) * 16;
    const uint32_t bOff   = (lane & 15) * 144 + (lane >> 4) * 16 + wn * 64;
    const uint32_t b1Addr = sb + G1_B1_OFF + bOff;
    const uint32_t b3Addr = sb + G1_B3_OFF + bOff;

    const int NC = HD / 32;
    for (int c = 0; c < NC; c++) {
        if (c + 1 < NC) { CP_WAIT1(); } else { CP_WAIT0(); }
        __syncthreads();
        if (c + 2 < NC)
            g1_load_stage(sb, (c + 2) % 3, c + 2, toks, W1h, W3h, n0, tid);

        const int s = c % 3;
        const uint32_t aS  = aAddr  + s * G1_A_STG;
        const uint32_t b1S = b1Addr + s * G1_B_STG;
        const uint32_t b3S = b3Addr + s * G1_B_STG;

        #pragma unroll
        for (int ks = 0; ks < 2; ks++) {
            uint32_t Af[2][4], B1f[2][4], B3f[2][4];
            ldmx4(Af[0], aS + ks * 32);
            ldmx4(Af[1], aS + ks * 32 + 16 * 80);
            ldmx4t(B1f[0], b1S + ks * 2304);
            ldmx4t(B1f[1], b1S + ks * 2304 + 32);
            ldmx4t(B3f[0], b3S + ks * 2304);
            ldmx4t(B3f[1], b3S + ks * 2304 + 32);
            #pragma unroll
            for (int nt = 0; nt < 4; nt++) {
                const uint32_t* b1 = &B1f[nt >> 1][(nt & 1) * 2];
                const uint32_t* b3 = &B3f[nt >> 1][(nt & 1) * 2];
                #pragma unroll
                for (int mt = 0; mt < 2; mt++) {
                    mma16(cg[mt][nt], Af[mt], b1);
                    mma16(cu[mt][nt], Af[mt], b3);
                }
            }
        }
    }

    // epilogue: h = silu(g) * u -> fp16 g_hh
    #pragma unroll
    for (int mt = 0; mt < 2; mt++) {
        #pragma unroll
        for (int half_ = 0; half_ < 2; half_++) {
            const int r = m0 + wm * 32 + mt * 16 + g + half_ * 8;
            if (r >= n) continue;
            __half2* hp = (__half2*)(g_hh + (size_t)(base + r) * FF + n0 + wn * 32 + 2 * tig);
            #pragma unroll
            for (int nt = 0; nt < 4; nt++) {
                float g0 = cg[mt][nt][half_ * 2 + 0], g1 = cg[mt][nt][half_ * 2 + 1];
                float u0 = cu[mt][nt][half_ * 2 + 0], u1 = cu[mt][nt][half_ * 2 + 1];
                float o0 = (g0 / (1.f + __expf(-g0))) * u0;
                float o1 = (g1 / (1.f + __expf(-g1))) * u1;
                hp[nt * 4] = __floats2half2_rn(o0, o1);
            }
        }
    }
}

// ======================= GEMM2 (fp16) =======================
// CTA 128M x 128N, BK=32, 3-stage. A [128 m][32 k] stride 80B; B [32 k][128 n] stride 272B.
#define G2_A_STG 10240
#define G2_B_OFF (3 * 10240)                  /* 30720 */
#define G2_B_STG 8704
#define G2_SMEM  (30720 + 3 * 8704)           /* 56832 */

__device__ __forceinline__ void g2_load_stage(uint32_t sb, int s, int c,
                                              const __half* __restrict__ W2h,
                                              int base, int m0, int n, int n0, int tid) {
    const int k0 = c * 32;
    const uint32_t aB = sb + s * G2_A_STG;
    #pragma unroll
    for (int q = 0; q < 2; q++) {               // 128 rows x 4 granules
        int id = q * 256 + tid, row = id >> 2, gq = id & 3;
        int rg = m0 + row; if (rg >= n) rg = n - 1;
        CP16(aB + row * 80 + gq * 16, g_hh + (size_t)(base + rg) * FF + k0 + gq * 8);
    }
    const uint32_t bB = sb + G2_B_OFF + s * G2_B_STG;
    #pragma unroll
    for (int q = 0; q < 2; q++) {               // 32 rows x 16 granules
        int id = q * 256 + tid, row = id >> 4, gq = id & 15;
        CP16(bB + row * 272 + gq * 16, W2h + (size_t)(k0 + row) * HD + n0 + gq * 8);
    }
    CP_COMMIT();
}

__global__ __launch_bounds__(256, 2) void gemm2_mma() {
    const int e = blockIdx.z;
    int n = 0, base = 0;
    #pragma unroll
    for (int i = 0; i < NE; i++) {
        int ci = g_counts[i];
        if (i < e) base += ci;
        if (i == e) n = ci;
    }
    const int m0 = blockIdx.y * 128;
    if (m0 >= n) return;
    const int n0 = blockIdx.x * 128;

    extern __shared__ char dynsmem[];
    const uint32_t sb = smem_u32(dynsmem);

    const int tid = threadIdx.x, wid = tid >> 5, lane = tid & 31;
    const int g = lane >> 2, tig = lane & 3;
    const int wm = wid >> 1, wn = wid & 1;

    const __half* __restrict__ W2h = g_w2h + (size_t)e * FF * HD;

    float cacc[2][8][4] = {};

    g2_load_stage(sb, 0, 0, W2h, base, m0, n, n0, tid);
    g2_load_stage(sb, 1, 1, W2h, base, m0, n, n0, tid);

    const uint32_t aAddr = sb + (wm * 32 + (lane & 15)) * 80 + (lane >> 4) * 16;
    const uint32_t bAddr = sb + G2_B_OFF + (lane & 15) * 272 + (lane >> 4) * 16 + wn * 128;

    const int NC = FF / 32;
    for (int c = 0; c < NC; c++) {
        if (c + 1 < NC) { CP_WAIT1(); } else { CP_WAIT0(); }
        __syncthreads();
        if (c + 2 < NC)
            g2_load_stage(sb, (c + 2) % 3, c + 2, W2h, base, m0, n, n0, tid);

        const int s = c % 3;
        const uint32_t aS = aAddr + s * G2_A_STG;
        const uint32_t bS = bAddr + s * G2_B_STG;

        #pragma unroll
        for (int ks = 0; ks < 2; ks++) {
            uint32_t Af[2][4], Bf[4][4];
            ldmx4(Af[0], aS + ks * 32);
            ldmx4(Af[1], aS + ks * 32 + 16 * 80);
            #pragma unroll
            for (int p = 0; p < 4; p++)
                ldmx4t(Bf[p], bS + ks * 4352 + p * 32);
            #pragma unroll
            for (int nt = 0; nt < 8; nt++) {
                const uint32_t* b = &Bf[nt >> 1][(nt & 1) * 2];
                #pragma unroll
                for (int mt = 0; mt < 2; mt++)
                    mma16(cacc[mt][nt], Af[mt], b);
            }
        }
    }

    #pragma unroll
    for (int mt = 0; mt < 2; mt++) {
        #pragma unroll
        for (int half_ = 0; half_ < 2; half_++) {
            const int r = m0 + wm * 32 + mt * 16 + g + half_ * 8;
            if (r >= n) continue;
            float* yp = g_y + (size_t)(base + r) * HD + n0 + wn * 64 + 2 * tig;
            #pragma unroll
            for (int nt = 0; nt < 8; nt++) {
                float2 o;
                o.x = cacc[mt][nt][half_ * 2 + 0];
                o.y = cacc[mt][nt][half_ * 2 + 1];
                *(float2*)(yp + nt * 8) = o;
            }
        }
    }
}

// ---------------- combine ----------------
__global__ void combine_kernel(float* __restrict__ out) {
    __shared__ int sbase[NE];
    if (threadIdx.x == 0) {
        int b = 0;
        #pragma unroll
        for (int e = 0; e < NE; e++) { sbase[e] = b; b += g_counts[e]; }
    }
    __syncthreads();
    const int idx = blockIdx.x * blockDim.x + threadIdx.x;
    const int t = idx / (HD / 4);
    const int c4 = idx % (HD / 4);
    float4 acc = make_float4(0.f, 0.f, 0.f, 0.f);
    #pragma unroll
    for (int k = 0; k < TOPK; k++) {
        int e = g_sel_e[t * 2 + k];
        int s = g_sel_s[t * 2 + k];
        float w = g_sel_w[t * 2 + k];
        const float4 v = *(const float4*)(g_y + (size_t)(sbase[e] + s) * HD + c4 * 4);
        acc.x += w * v.x; acc.y += w * v.y; acc.z += w * v.z; acc.w += w * v.w;
    }
    *(float4*)(out + (size_t)t * HD + c4 * 4) = acc;
}

// ---------------- launcher ----------------
extern "C" void kernel_launch(void* const* d_in, const int* in_sizes, int n_in,
                              void* d_out, int out_size) {
    const float* x  = (const float*)d_in[0];
    const float* Wg = (const float*)d_in[1];
    const float* bg = (const float*)d_in[2];
    const float* W1 = (const float*)d_in[3];
    const float* W3 = (const float*)d_in[4];
    const float* W2 = (const float*)d_in[5];
    float* out = (float*)d_out;

    cudaFuncSetAttribute(gemm1_mma, cudaFuncAttributeMaxDynamicSharedMemorySize, G1_SMEM);
    cudaFuncSetAttribute(gemm2_mma, cudaFuncAttributeMaxDynamicSharedMemorySize, G2_SMEM);

    const int wN4 = NE * HD * FF / 4;
    const int xN4 = TOK * HD / 4;

    // launch index 3 = gemm1 (ncu capture slot)
    cvt_x_kernel<<<(xN4 + 255) / 256, 256>>>((const float4*)x);               // 0 (+zero counters)
    routing_kernel<<<TOK, 256>>>(x, Wg, bg);                                  // 1
    cvt_w13_kernel<<<(2 * wN4) / 256, 256>>>((const float4*)W1, (const float4*)W3); // 2
    gemm1_mma<<<dim3(FF / 64, TOK / 128, NE), 256, G1_SMEM>>>();              // 3
    cvt_w2_kernel<<<wN4 / 256, 256>>>((const float4*)W2);                     // 4
    gemm2_mma<<<dim3(HD / 128, TOK / 128, NE), 256, G2_SMEM>>>();             // 5
    combine_kernel<<<(TOK * (HD / 4)) / 256, 256>>>(out);                     // 6
}

// round 9
// speedup vs baseline: 2.2859x; 1.1056x over previous
#include <cuda_runtime.h>
#include <cuda_fp16.h>
#include <cstdint>

#define TOK 4096   // B*S tokens
#define HD  1024
#define NE  8
#define FF  4096
#define TOPK 2

// ---------------- scratch (device globals) ----------------
__device__ int   g_counts[NE];
__device__ int   g_tok[NE][TOK];
__device__ int   g_sel_e[TOK * TOPK];
__device__ int   g_sel_s[TOK * TOPK];
__device__ float g_sel_w[TOK * TOPK];
__device__ float g_y[(size_t)TOK * TOPK * HD];
// fp16 operand copies (natural layouts)
__device__ __align__(16) __half g_xh[(size_t)TOK * HD];          // [t][k]
__device__ __align__(16) __half g_w1h[(size_t)NE * HD * FF];     // [e][k][n]
__device__ __align__(16) __half g_w3h[(size_t)NE * HD * FF];
__device__ __align__(16) __half g_w2h[(size_t)NE * FF * HD];     // [e][k][n]
__device__ __align__(16) __half g_hh[(size_t)TOK * TOPK * FF];   // SwiGLU out, fp16

// ---------------- helpers ----------------
__device__ __forceinline__ uint32_t smem_u32(const void* p) {
    uint32_t a;
    asm("{ .reg .u64 t; cvta.to.shared.u64 t, %1; cvt.u32.u64 %0, t; }" : "=r"(a) : "l"(p));
    return a;
}
__device__ __forceinline__ void mma16(float* d, const uint32_t* a, const uint32_t* b) {
    asm volatile("mma.sync.aligned.m16n8k16.row.col.f32.f16.f16.f32 "
        "{%0,%1,%2,%3}, {%4,%5,%6,%7}, {%8,%9}, {%0,%1,%2,%3};"
        : "+f"(d[0]), "+f"(d[1]), "+f"(d[2]), "+f"(d[3])
        : "r"(a[0]), "r"(a[1]), "r"(a[2]), "r"(a[3]), "r"(b[0]), "r"(b[1]));
}
__device__ __forceinline__ void ldmx4(uint32_t* r, uint32_t addr) {
    asm volatile("ldmatrix.sync.aligned.m8n8.x4.shared.b16 {%0,%1,%2,%3}, [%4];"
        : "=r"(r[0]), "=r"(r[1]), "=r"(r[2]), "=r"(r[3]) : "r"(addr));
}
__device__ __forceinline__ void ldmx4t(uint32_t* r, uint32_t addr) {
    asm volatile("ldmatrix.sync.aligned.m8n8.x4.trans.shared.b16 {%0,%1,%2,%3}, [%4];"
        : "=r"(r[0]), "=r"(r[1]), "=r"(r[2]), "=r"(r[3]) : "r"(addr));
}
#define CP16(dst32, src) \
    asm volatile("cp.async.cg.shared.global [%0], [%1], 16;" :: "r"(dst32), "l"(src) : "memory")
#define CP_COMMIT() asm volatile("cp.async.commit_group;" ::: "memory")
#define CP_WAIT0()  asm volatile("cp.async.wait_group 0;" ::: "memory")
#define CP_WAIT1()  asm volatile("cp.async.wait_group 1;" ::: "memory")
__device__ __forceinline__ uint32_t h2u(__half2 h) { return *reinterpret_cast<uint32_t*>(&h); }

// ---------------- prep: fp32 -> fp16 converts ----------------
__global__ void cvt_x_kernel(const float4* __restrict__ x) {
    int i = blockIdx.x * blockDim.x + threadIdx.x;
    if (blockIdx.x == 0 && threadIdx.x < NE) g_counts[threadIdx.x] = 0;
    if (i < TOK * HD / 4) {
        float4 v = x[i];
        uint2 o;
        o.x = h2u(__floats2half2_rn(v.x, v.y));
        o.y = h2u(__floats2half2_rn(v.z, v.w));
        ((uint2*)g_xh)[i] = o;
    }
}
__global__ void cvt_w13_kernel(const float4* __restrict__ W1, const float4* __restrict__ W3) {
    const int n4 = NE * HD * FF / 4;
    int i = blockIdx.x * blockDim.x + threadIdx.x;
    const float4* s = (i < n4) ? W1 : W3;
    uint2* d = (i < n4) ? (uint2*)g_w1h : (uint2*)g_w3h;
    int j = (i < n4) ? i : i - n4;
    float4 v = s[j];
    uint2 o;
    o.x = h2u(__floats2half2_rn(v.x, v.y));
    o.y = h2u(__floats2half2_rn(v.z, v.w));
    d[j] = o;
}
__global__ void cvt_w2_kernel(const float4* __restrict__ W2) {
    int i = blockIdx.x * blockDim.x + threadIdx.x;
    float4 v = W2[i];
    uint2 o;
    o.x = h2u(__floats2half2_rn(v.x, v.y));
    o.y = h2u(__floats2half2_rn(v.z, v.w));
    ((uint2*)g_w2h)[i] = o;
}

// ---------------- routing ----------------
__global__ void routing_kernel(const float* __restrict__ x,
                               const float* __restrict__ Wg,
                               const float* __restrict__ bg) {
    const int t = blockIdx.x, tid = threadIdx.x, wid = tid >> 5, lid = tid & 31;
    __shared__ float s_logit[NE];
    const float* xt = x + (size_t)t * HD;
    float acc = 0.f;
    for (int h = lid; h < HD; h += 32) acc += xt[h] * Wg[h * NE + wid];
    #pragma unroll
    for (int o = 16; o > 0; o >>= 1) acc += __shfl_down_sync(0xFFFFFFFFu, acc, o);
    if (lid == 0) s_logit[wid] = acc + bg[wid];
    __syncthreads();
    if (tid == 0) {
        float l[NE];
        #pragma unroll
        for (int e = 0; e < NE; e++) l[e] = s_logit[e];
        int i0 = 0;
        #pragma unroll
        for (int e = 1; e < NE; e++) if (l[e] > l[i0]) i0 = e;
        int i1 = (i0 == 0) ? 1 : 0;
        #pragma unroll
        for (int e = 0; e < NE; e++) if (e != i0 && l[e] > l[i1]) i1 = e;
        float w1 = __expf(l[i1] - l[i0]);
        float inv = 1.f / (1.f + w1);
        int s0 = atomicAdd(&g_counts[i0], 1);
        int s1 = atomicAdd(&g_counts[i1], 1);
        g_tok[i0][s0] = t;  g_tok[i1][s1] = t;
        g_sel_e[t*2+0] = i0; g_sel_s[t*2+0] = s0; g_sel_w[t*2+0] = inv;
        g_sel_e[t*2+1] = i1; g_sel_s[t*2+1] = s1; g_sel_w[t*2+1] = w1 * inv;
    }
}

// ======================= GEMM1 (fp16, BK=64) =======================
// CTA 128M x 64N fused (W1,W3), 3-stage cp.async, 2 CTA/SM, frag double-buffer.
// A smem: [128 m][64 k halves], row stride 144B (banks 4r — CF).
// B smem: [64 k][64 n halves], row stride 144B (CF).
#define G1_A_OFF  512
#define G1_A_STG  18432
#define G1_B1_OFF (512 + 3 * 18432)           /* 55808 */
#define G1_B_STG  9216
#define G1_B3_OFF (55808 + 3 * 9216)          /* 83456 */
#define G1_SMEM   (83456 + 3 * 9216)          /* 111104 */

__device__ __forceinline__ void g1_load_stage(uint32_t sb, int s, int c,
                                              const int* toks,
                                              const __half* __restrict__ W1h,
                                              const __half* __restrict__ W3h,
                                              int n0, int tid) {
    const int k0 = c * 64;
    const uint32_t aB = sb + G1_A_OFF + s * G1_A_STG;
    #pragma unroll
    for (int q = 0; q < 4; q++) {               // 128 rows x 8 granules, 4/thread
        int id = q * 256 + tid, row = id >> 3, gq = id & 7;
        CP16(aB + row * 144 + gq * 16, g_xh + (size_t)toks[row] * HD + k0 + gq * 8);
    }
    const uint32_t b1B = sb + G1_B1_OFF + s * G1_B_STG;
    const uint32_t b3B = sb + G1_B3_OFF + s * G1_B_STG;
    #pragma unroll
    for (int q = 0; q < 2; q++) {               // 64 k-rows x 8 granules, 2/thread each
        int id = q * 256 + tid, row = id >> 3, gq = id & 7;
        size_t off = (size_t)(k0 + row) * FF + n0 + gq * 8;
        uint32_t so = row * 144 + gq * 16;
        CP16(b1B + so, W1h + off);
        CP16(b3B + so, W3h + off);
    }
    CP_COMMIT();
}

__global__ __launch_bounds__(256, 2) void gemm1_mma() {
    const int e = blockIdx.z;
    int n = 0, base = 0;
    #pragma unroll
    for (int i = 0; i < NE; i++) {
        int ci = g_counts[i];
        if (i < e) base += ci;
        if (i == e) n = ci;
    }
    const int m0 = blockIdx.y * 128;
    if (m0 >= n) return;
    const int n0 = blockIdx.x * 64;

    extern __shared__ char dynsmem[];
    const uint32_t sb = smem_u32(dynsmem);
    int* toks = (int*)dynsmem;

    const int tid = threadIdx.x, wid = tid >> 5, lane = tid & 31;
    const int g = lane >> 2, tig = lane & 3;
    const int wm = wid >> 1, wn = wid & 1;

    if (tid < 128) { int r = m0 + tid; toks[tid] = g_tok[e][r < n ? r : n - 1]; }
    __syncthreads();

    const __half* __restrict__ W1h = g_w1h + (size_t)e * HD * FF;
    const __half* __restrict__ W3h = g_w3h + (size_t)e * HD * FF;

    float cg[2][4][4] = {};
    float cu[2][4][4] = {};

    g1_load_stage(sb, 0, 0, toks, W1h, W3h, n0, tid);
    g1_load_stage(sb, 1, 1, toks, W1h, W3h, n0, tid);

    const uint32_t aAddr  = sb + G1_A_OFF + (wm * 32 + (lane & 15)) * 144 + (lane >> 4) * 16;
    const uint32_t bOff   = (lane & 15) * 144 + (lane >> 4) * 16 + wn * 64;
    const uint32_t b1Addr = sb + G1_B1_OFF + bOff;
    const uint32_t b3Addr = sb + G1_B3_OFF + bOff;

    const int NC = HD / 64;   // 16 chunks
    for (int c = 0; c < NC; c++) {
        if (c + 1 < NC) { CP_WAIT1(); } else { CP_WAIT0(); }
        __syncthreads();
        if (c + 2 < NC)
            g1_load_stage(sb, (c + 2) % 3, c + 2, toks, W1h, W3h, n0, tid);

        const int s = c % 3;
        const uint32_t aS  = aAddr  + s * G1_A_STG;
        const uint32_t b1S = b1Addr + s * G1_B_STG;
        const uint32_t b3S = b3Addr + s * G1_B_STG;

        uint32_t Af[2][2][4], B1f[2][2][4], B3f[2][2][4];
        // prime ks=0 fragments
        ldmx4(Af[0][0], aS);
        ldmx4(Af[0][1], aS + 16 * 144);
        ldmx4t(B1f[0][0], b1S);
        ldmx4t(B1f[0][1], b1S + 32);
        ldmx4t(B3f[0][0], b3S);
        ldmx4t(B3f[0][1], b3S + 32);

        #pragma unroll
        for (int ks = 0; ks < 4; ks++) {
            const int cur = ks & 1;
            if (ks < 3) {
                const int nxt = cur ^ 1;
                const uint32_t ao = aS + (ks + 1) * 32;
                const uint32_t bo = (ks + 1) * 2304;
                ldmx4(Af[nxt][0], ao);
                ldmx4(Af[nxt][1], ao + 16 * 144);
                ldmx4t(B1f[nxt][0], b1S + bo);
                ldmx4t(B1f[nxt][1], b1S + bo + 32);
                ldmx4t(B3f[nxt][0], b3S + bo);
                ldmx4t(B3f[nxt][1], b3S + bo + 32);
            }
            #pragma unroll
            for (int nt = 0; nt < 4; nt++) {
                const uint32_t* b1 = &B1f[cur][nt >> 1][(nt & 1) * 2];
                const uint32_t* b3 = &B3f[cur][nt >> 1][(nt & 1) * 2];
                #pragma unroll
                for (int mt = 0; mt < 2; mt++) {
                    mma16(cg[mt][nt], Af[cur][mt], b1);
                    mma16(cu[mt][nt], Af[cur][mt], b3);
                }
            }
        }
    }

    // epilogue: h = silu(g) * u -> fp16 g_hh
    #pragma unroll
    for (int mt = 0; mt < 2; mt++) {
        #pragma unroll
        for (int half_ = 0; half_ < 2; half_++) {
            const int r = m0 + wm * 32 + mt * 16 + g + half_ * 8;
            if (r >= n) continue;
            __half2* hp = (__half2*)(g_hh + (size_t)(base + r) * FF + n0 + wn * 32 + 2 * tig);
            #pragma unroll
            for (int nt = 0; nt < 4; nt++) {
                float g0 = cg[mt][nt][half_ * 2 + 0], g1 = cg[mt][nt][half_ * 2 + 1];
                float u0 = cu[mt][nt][half_ * 2 + 0], u1 = cu[mt][nt][half_ * 2 + 1];
                float o0 = (g0 / (1.f + __expf(-g0))) * u0;
                float o1 = (g1 / (1.f + __expf(-g1))) * u1;
                hp[nt * 4] = __floats2half2_rn(o0, o1);
            }
        }
    }
}

// ======================= GEMM2 (fp16, BK=64) =======================
// CTA 128M x 128N, 3-stage, frag double-buffer.
// A [128 m][64 k] stride 144B; B [64 k][128 n] stride 272B.
#define G2_A_STG 18432
#define G2_B_OFF (3 * 18432)                  /* 55296 */
#define G2_B_STG 17408
#define G2_SMEM  (55296 + 3 * 17408)          /* 107520 */

__device__ __forceinline__ void g2_load_stage(uint32_t sb, int s, int c,
                                              const __half* __restrict__ W2h,
                                              int base, int m0, int n, int n0, int tid) {
    const int k0 = c * 64;
    const uint32_t aB = sb + s * G2_A_STG;
    #pragma unroll
    for (int q = 0; q < 4; q++) {               // 128 rows x 8 granules
        int id = q * 256 + tid, row = id >> 3, gq = id & 7;
        int rg = m0 + row; if (rg >= n) rg = n - 1;
        CP16(aB + row * 144 + gq * 16, g_hh + (size_t)(base + rg) * FF + k0 + gq * 8);
    }
    const uint32_t bB = sb + G2_B_OFF + s * G2_B_STG;
    #pragma unroll
    for (int q = 0; q < 4; q++) {               // 64 k-rows x 16 granules
        int id = q * 256 + tid, row = id >> 4, gq = id & 15;
        CP16(bB + row * 272 + gq * 16, W2h + (size_t)(k0 + row) * HD + n0 + gq * 8);
    }
    CP_COMMIT();
}

__global__ __launch_bounds__(256, 2) void gemm2_mma() {
    const int e = blockIdx.z;
    int n = 0, base = 0;
    #pragma unroll
    for (int i = 0; i < NE; i++) {
        int ci = g_counts[i];
        if (i < e) base += ci;
        if (i == e) n = ci;
    }
    const int m0 = blockIdx.y * 128;
    if (m0 >= n) return;
    const int n0 = blockIdx.x * 128;

    extern __shared__ char dynsmem[];
    const uint32_t sb = smem_u32(dynsmem);

    const int tid = threadIdx.x, wid = tid >> 5, lane = tid & 31;
    const int g = lane >> 2, tig = lane & 3;
    const int wm = wid >> 1, wn = wid & 1;

    const __half* __restrict__ W2h = g_w2h + (size_t)e * FF * HD;

    float cacc[2][8][4] = {};

    g2_load_stage(sb, 0, 0, W2h, base, m0, n, n0, tid);
    g2_load_stage(sb, 1, 1, W2h, base, m0, n, n0, tid);

    const uint32_t aAddr = sb + (wm * 32 + (lane & 15)) * 144 + (lane >> 4) * 16;
    const uint32_t bAddr = sb + G2_B_OFF + (lane & 15) * 272 + (lane >> 4) * 16 + wn * 128;

    const int NC = FF / 64;   // 64 chunks
    for (int c = 0; c < NC; c++) {
        if (c + 1 < NC) { CP_WAIT1(); } else { CP_WAIT0(); }
        __syncthreads();
        if (c + 2 < NC)
            g2_load_stage(sb, (c + 2) % 3, c + 2, W2h, base, m0, n, n0, tid);

        const int s = c % 3;
        const uint32_t aS = aAddr + s * G2_A_STG;
        const uint32_t bS = bAddr + s * G2_B_STG;

        uint32_t Af[2][2][4], Bf[2][4][4];
        ldmx4(Af[0][0], aS);
        ldmx4(Af[0][1], aS + 16 * 144);
        #pragma unroll
        for (int p = 0; p < 4; p++)
            ldmx4t(Bf[0][p], bS + p * 32);

        #pragma unroll
        for (int ks = 0; ks < 4; ks++) {
            const int cur = ks & 1;
            if (ks < 3) {
                const int nxt = cur ^ 1;
                const uint32_t ao = aS + (ks + 1) * 32;
                const uint32_t bo = bS + (ks + 1) * 4352;
                ldmx4(Af[nxt][0], ao);
                ldmx4(Af[nxt][1], ao + 16 * 144);
                #pragma unroll
                for (int p = 0; p < 4; p++)
                    ldmx4t(Bf[nxt][p], bo + p * 32);
            }
            #pragma unroll
            for (int nt = 0; nt < 8; nt++) {
                const uint32_t* b = &Bf[cur][nt >> 1][(nt & 1) * 2];
                #pragma unroll
                for (int mt = 0; mt < 2; mt++)
                    mma16(cacc[mt][nt], Af[cur][mt], b);
            }
        }
    }

    #pragma unroll
    for (int mt = 0; mt < 2; mt++) {
        #pragma unroll
        for (int half_ = 0; half_ < 2; half_++) {
            const int r = m0 + wm * 32 + mt * 16 + g + half_ * 8;
            if (r >= n) continue;
            float* yp = g_y + (size_t)(base + r) * HD + n0 + wn * 64 + 2 * tig;
            #pragma unroll
            for (int nt = 0; nt < 8; nt++) {
                float2 o;
                o.x = cacc[mt][nt][half_ * 2 + 0];
                o.y = cacc[mt][nt][half_ * 2 + 1];
                *(float2*)(yp + nt * 8) = o;
            }
        }
    }
}

// ---------------- combine ----------------
__global__ void combine_kernel(float* __restrict__ out) {
    __shared__ int sbase[NE];
    if (threadIdx.x == 0) {
        int b = 0;
        #pragma unroll
        for (int e = 0; e < NE; e++) { sbase[e] = b; b += g_counts[e]; }
    }
    __syncthreads();
    const int idx = blockIdx.x * blockDim.x + threadIdx.x;
    const int t = idx / (HD / 4);
    const int c4 = idx % (HD / 4);
    float4 acc = make_float4(0.f, 0.f, 0.f, 0.f);
    #pragma unroll
    for (int k = 0; k < TOPK; k++) {
        int e = g_sel_e[t * 2 + k];
        int s = g_sel_s[t * 2 + k];
        float w = g_sel_w[t * 2 + k];
        const float4 v = *(const float4*)(g_y + (size_t)(sbase[e] + s) * HD + c4 * 4);
        acc.x += w * v.x; acc.y += w * v.y; acc.z += w * v.z; acc.w += w * v.w;
    }
    *(float4*)(out + (size_t)t * HD + c4 * 4) = acc;
}

// ---------------- launcher ----------------
extern "C" void kernel_launch(void* const* d_in, const int* in_sizes, int n_in,
                              void* d_out, int out_size) {
    const float* x  = (const float*)d_in[0];
    const float* Wg = (const float*)d_in[1];
    const float* bg = (const float*)d_in[2];
    const float* W1 = (const float*)d_in[3];
    const float* W3 = (const float*)d_in[4];
    const float* W2 = (const float*)d_in[5];
    float* out = (float*)d_out;

    cudaFuncSetAttribute(gemm1_mma, cudaFuncAttributeMaxDynamicSharedMemorySize, G1_SMEM);
    cudaFuncSetAttribute(gemm2_mma, cudaFuncAttributeMaxDynamicSharedMemorySize, G2_SMEM);

    const int wN4 = NE * HD * FF / 4;
    const int xN4 = TOK * HD / 4;

    // launch index 3 = gemm1 (ncu capture slot)
    cvt_x_kernel<<<(xN4 + 255) / 256, 256>>>((const float4*)x);               // 0 (+zero counters)
    routing_kernel<<<TOK, 256>>>(x, Wg, bg);                                  // 1
    cvt_w13_kernel<<<(2 * wN4) / 256, 256>>>((const float4*)W1, (const float4*)W3); // 2
    gemm1_mma<<<dim3(FF / 64, TOK / 128, NE), 256, G1_SMEM>>>();              // 3
    cvt_w2_kernel<<<wN4 / 256, 256>>>((const float4*)W2);                     // 4
    gemm2_mma<<<dim3(HD / 128, TOK / 128, NE), 256, G2_SMEM>>>();             // 5
    combine_kernel<<<(TOK * (HD / 4)) / 256, 256>>>(out);                     // 6
}

// round 10
// speedup vs baseline: 2.3278x; 1.0183x over previous
#include <cuda_runtime.h>
#include <cuda_fp16.h>
#include <cstdint>

#define TOK 4096   // B*S tokens
#define HD  1024
#define NE  8
#define FF  4096
#define TOPK 2

// ---------------- scratch (device globals) ----------------
__device__ int   g_counts[NE];
__device__ int   g_tok[NE][TOK];
__device__ int   g_sel_e[TOK * TOPK];
__device__ int   g_sel_s[TOK * TOPK];
__device__ float g_sel_w[TOK * TOPK];
__device__ float g_y[(size_t)TOK * TOPK * HD];
// fp16 operand copies (natural layouts)
__device__ __align__(16) __half g_xh[(size_t)TOK * HD];          // [t][k]
__device__ __align__(16) __half g_w1h[(size_t)NE * HD * FF];     // [e][k][n]
__device__ __align__(16) __half g_w3h[(size_t)NE * HD * FF];
__device__ __align__(16) __half g_w2h[(size_t)NE * FF * HD];     // [e][k][n]
__device__ __align__(16) __half g_hh[(size_t)TOK * TOPK * FF];   // SwiGLU out, fp16

// ---------------- helpers ----------------
__device__ __forceinline__ uint32_t smem_u32(const void* p) {
    uint32_t a;
    asm("{ .reg .u64 t; cvta.to.shared.u64 t, %1; cvt.u32.u64 %0, t; }" : "=r"(a) : "l"(p));
    return a;
}
__device__ __forceinline__ void mma16(float* d, const uint32_t* a, const uint32_t* b) {
    asm volatile("mma.sync.aligned.m16n8k16.row.col.f32.f16.f16.f32 "
        "{%0,%1,%2,%3}, {%4,%5,%6,%7}, {%8,%9}, {%0,%1,%2,%3};"
        : "+f"(d[0]), "+f"(d[1]), "+f"(d[2]), "+f"(d[3])
        : "r"(a[0]), "r"(a[1]), "r"(a[2]), "r"(a[3]), "r"(b[0]), "r"(b[1]));
}
__device__ __forceinline__ void ldmx4(uint32_t* r, uint32_t addr) {
    asm volatile("ldmatrix.sync.aligned.m8n8.x4.shared.b16 {%0,%1,%2,%3}, [%4];"
        : "=r"(r[0]), "=r"(r[1]), "=r"(r[2]), "=r"(r[3]) : "r"(addr));
}
__device__ __forceinline__ void ldmx4t(uint32_t* r, uint32_t addr) {
    asm volatile("ldmatrix.sync.aligned.m8n8.x4.trans.shared.b16 {%0,%1,%2,%3}, [%4];"
        : "=r"(r[0]), "=r"(r[1]), "=r"(r[2]), "=r"(r[3]) : "r"(addr));
}
#define CP16(dst32, src) \
    asm volatile("cp.async.cg.shared.global [%0], [%1], 16;" :: "r"(dst32), "l"(src) : "memory")
#define CP_COMMIT() asm volatile("cp.async.commit_group;" ::: "memory")
#define CP_WAIT0()  asm volatile("cp.async.wait_group 0;" ::: "memory")
#define CP_WAIT1()  asm volatile("cp.async.wait_group 1;" ::: "memory")
#define CP_WAIT2()  asm volatile("cp.async.wait_group 2;" ::: "memory")
__device__ __forceinline__ uint32_t h2u(__half2 h) { return *reinterpret_cast<uint32_t*>(&h); }
__device__ __forceinline__ float silu_mul(float g, float u) {
    return __fdividef(g, 1.f + __expf(-g)) * u;
}

// ---------------- kernel 0: zero counters ----------------
__global__ void zero_counts_kernel() {
    if (threadIdx.x < NE) g_counts[threadIdx.x] = 0;
}

// ---------------- routing + x fp16 convert ----------------
__global__ void routing_kernel(const float* __restrict__ x,
                               const float* __restrict__ Wg,
                               const float* __restrict__ bg) {
    const int t = blockIdx.x, tid = threadIdx.x, wid = tid >> 5, lid = tid & 31;
    __shared__ float s_logit[NE];
    const float* xt = x + (size_t)t * HD;

    // fp16 convert of this token's row (256 threads x float4)
    {
        float4 v = ((const float4*)xt)[tid];
        uint2 o;
        o.x = h2u(__floats2half2_rn(v.x, v.y));
        o.y = h2u(__floats2half2_rn(v.z, v.w));
        ((uint2*)(g_xh + (size_t)t * HD))[tid] = o;
    }

    float acc = 0.f;
    for (int h = lid; h < HD; h += 32) acc += xt[h] * Wg[h * NE + wid];
    #pragma unroll
    for (int o = 16; o > 0; o >>= 1) acc += __shfl_down_sync(0xFFFFFFFFu, acc, o);
    if (lid == 0) s_logit[wid] = acc + bg[wid];
    __syncthreads();
    if (tid == 0) {
        float l[NE];
        #pragma unroll
        for (int e = 0; e < NE; e++) l[e] = s_logit[e];
        int i0 = 0;
        #pragma unroll
        for (int e = 1; e < NE; e++) if (l[e] > l[i0]) i0 = e;
        int i1 = (i0 == 0) ? 1 : 0;
        #pragma unroll
        for (int e = 0; e < NE; e++) if (e != i0 && l[e] > l[i1]) i1 = e;
        float w1 = __expf(l[i1] - l[i0]);
        float inv = __fdividef(1.f, 1.f + w1);
        int s0 = atomicAdd(&g_counts[i0], 1);
        int s1 = atomicAdd(&g_counts[i1], 1);
        g_tok[i0][s0] = t;  g_tok[i1][s1] = t;
        g_sel_e[t*2+0] = i0; g_sel_s[t*2+0] = s0; g_sel_w[t*2+0] = inv;
        g_sel_e[t*2+1] = i1; g_sel_s[t*2+1] = s1; g_sel_w[t*2+1] = w1 * inv;
    }
}

// ---------------- prep: weight fp16 converts ----------------
__global__ void cvt_w13_kernel(const float4* __restrict__ W1, const float4* __restrict__ W3) {
    const int n4 = NE * HD * FF / 4;
    int i = blockIdx.x * blockDim.x + threadIdx.x;
    const float4* s = (i < n4) ? W1 : W3;
    uint2* d = (i < n4) ? (uint2*)g_w1h : (uint2*)g_w3h;
    int j = (i < n4) ? i : i - n4;
    float4 v = s[j];
    uint2 o;
    o.x = h2u(__floats2half2_rn(v.x, v.y));
    o.y = h2u(__floats2half2_rn(v.z, v.w));
    d[j] = o;
}
__global__ void cvt_w2_kernel(const float4* __restrict__ W2) {
    int i = blockIdx.x * blockDim.x + threadIdx.x;
    float4 v = W2[i];
    uint2 o;
    o.x = h2u(__floats2half2_rn(v.x, v.y));
    o.y = h2u(__floats2half2_rn(v.z, v.w));
    ((uint2*)g_w2h)[i] = o;
}

// ======================= GEMM1 (fp16, BK=64) =======================
// CTA 128M x 64N fused (W1,W3), 3-stage cp.async, 2 CTA/SM, frag double-buffer,
// cross-chunk fragment priming.
#define G1_A_OFF  512
#define G1_A_STG  18432
#define G1_B1_OFF (512 + 3 * 18432)           /* 55808 */
#define G1_B_STG  9216
#define G1_B3_OFF (55808 + 3 * 9216)          /* 83456 */
#define G1_SMEM   (83456 + 3 * 9216)          /* 111104 */

__device__ __forceinline__ void g1_load_stage(uint32_t sb, int s, int c,
                                              const int* toks,
                                              const __half* __restrict__ W1h,
                                              const __half* __restrict__ W3h,
                                              int n0, int tid) {
    const int k0 = c * 64;
    const uint32_t aB = sb + G1_A_OFF + s * G1_A_STG;
    #pragma unroll
    for (int q = 0; q < 4; q++) {               // 128 rows x 8 granules, 4/thread
        int id = q * 256 + tid, row = id >> 3, gq = id & 7;
        CP16(aB + row * 144 + gq * 16, g_xh + (size_t)toks[row] * HD + k0 + gq * 8);
    }
    const uint32_t b1B = sb + G1_B1_OFF + s * G1_B_STG;
    const uint32_t b3B = sb + G1_B3_OFF + s * G1_B_STG;
    #pragma unroll
    for (int q = 0; q < 2; q++) {               // 64 k-rows x 8 granules, 2/thread each
        int id = q * 256 + tid, row = id >> 3, gq = id & 7;
        size_t off = (size_t)(k0 + row) * FF + n0 + gq * 8;
        uint32_t so = row * 144 + gq * 16;
        CP16(b1B + so, W1h + off);
        CP16(b3B + so, W3h + off);
    }
    CP_COMMIT();
}

__global__ __launch_bounds__(256, 2) void gemm1_mma() {
    const int e = blockIdx.z;
    int n = 0, base = 0;
    #pragma unroll
    for (int i = 0; i < NE; i++) {
        int ci = g_counts[i];
        if (i < e) base += ci;
        if (i == e) n = ci;
    }
    const int m0 = blockIdx.y * 128;
    if (m0 >= n) return;
    const int n0 = blockIdx.x * 64;

    extern __shared__ char dynsmem[];
    const uint32_t sb = smem_u32(dynsmem);
    int* toks = (int*)dynsmem;

    const int tid = threadIdx.x, wid = tid >> 5, lane = tid & 31;
    const int g = lane >> 2, tig = lane & 3;
    const int wm = wid >> 1, wn = wid & 1;

    if (tid < 128) { int r = m0 + tid; toks[tid] = g_tok[e][r < n ? r : n - 1]; }
    __syncthreads();

    const __half* __restrict__ W1h = g_w1h + (size_t)e * HD * FF;
    const __half* __restrict__ W3h = g_w3h + (size_t)e * HD * FF;

    float cg[2][4][4] = {};
    float cu[2][4][4] = {};

    const uint32_t aAddr  = sb + G1_A_OFF + (wm * 32 + (lane & 15)) * 144 + (lane >> 4) * 16;
    const uint32_t bOff   = (lane & 15) * 144 + (lane >> 4) * 16 + wn * 64;
    const uint32_t b1Addr = sb + G1_B1_OFF + bOff;
    const uint32_t b3Addr = sb + G1_B3_OFF + bOff;

    uint32_t Af[2][2][4], B1f[2][2][4], B3f[2][2][4];

    // prologue: 3 stages in flight, prime chunk 0 frags
    g1_load_stage(sb, 0, 0, toks, W1h, W3h, n0, tid);
    g1_load_stage(sb, 1, 1, toks, W1h, W3h, n0, tid);
    g1_load_stage(sb, 2, 2, toks, W1h, W3h, n0, tid);
    CP_WAIT2();
    __syncthreads();
    ldmx4(Af[0][0], aAddr);
    ldmx4(Af[0][1], aAddr + 16 * 144);
    ldmx4t(B1f[0][0], b1Addr);
    ldmx4t(B1f[0][1], b1Addr + 32);
    ldmx4t(B3f[0][0], b3Addr);
    ldmx4t(B3f[0][1], b3Addr + 32);

    const int NC = HD / 64;   // 16 chunks
    for (int c = 0; c < NC; c++) {
        const int s = c % 3;
        const uint32_t aS  = aAddr  + s * G1_A_STG;
        const uint32_t b1S = b1Addr + s * G1_B_STG;
        const uint32_t b3S = b3Addr + s * G1_B_STG;

        #pragma unroll
        for (int ks = 0; ks < 4; ks++) {
            const int cur = ks & 1;
            if (ks < 3) {
                const int nxt = cur ^ 1;
                const uint32_t ao = aS + (ks + 1) * 32;
                const uint32_t bo = (ks + 1) * 2304;
                ldmx4(Af[nxt][0], ao);
                ldmx4(Af[nxt][1], ao + 16 * 144);
                ldmx4t(B1f[nxt][0], b1S + bo);
                ldmx4t(B1f[nxt][1], b1S + bo + 32);
                ldmx4t(B3f[nxt][0], b3S + bo);
                ldmx4t(B3f[nxt][1], b3S + bo + 32);
            }
            #pragma unroll
            for (int nt = 0; nt < 4; nt++) {
                const uint32_t* b1 = &B1f[cur][nt >> 1][(nt & 1) * 2];
                const uint32_t* b3 = &B3f[cur][nt >> 1][(nt & 1) * 2];
                #pragma unroll
                for (int mt = 0; mt < 2; mt++) {
                    mma16(cg[mt][nt], Af[cur][mt], b1);
                    mma16(cu[mt][nt], Af[cur][mt], b3);
                }
            }
        }

        if (c + 1 < NC) {
            if (c + 2 < NC) { CP_WAIT1(); } else { CP_WAIT0(); }
            __syncthreads();
            // prime chunk c+1 frags (stage (c+1)%3)
            const int s1 = (c + 1) % 3;
            const uint32_t aN  = aAddr  + s1 * G1_A_STG;
            const uint32_t b1N = b1Addr + s1 * G1_B_STG;
            const uint32_t b3N = b3Addr + s1 * G1_B_STG;
            ldmx4(Af[0][0], aN);
            ldmx4(Af[0][1], aN + 16 * 144);
            ldmx4t(B1f[0][0], b1N);
            ldmx4t(B1f[0][1], b1N + 32);
            ldmx4t(B3f[0][0], b3N);
            ldmx4t(B3f[0][1], b3N + 32);
            if (c + 3 < NC)
                g1_load_stage(sb, s, c + 3, toks, W1h, W3h, n0, tid);
        }
    }

    // epilogue: h = silu(g) * u -> fp16 g_hh (fast div)
    #pragma unroll
    for (int mt = 0; mt < 2; mt++) {
        #pragma unroll
        for (int half_ = 0; half_ < 2; half_++) {
            const int r = m0 + wm * 32 + mt * 16 + g + half_ * 8;
            if (r >= n) continue;
            __half2* hp = (__half2*)(g_hh + (size_t)(base + r) * FF + n0 + wn * 32 + 2 * tig);
            #pragma unroll
            for (int nt = 0; nt < 4; nt++) {
                float o0 = silu_mul(cg[mt][nt][half_ * 2 + 0], cu[mt][nt][half_ * 2 + 0]);
                float o1 = silu_mul(cg[mt][nt][half_ * 2 + 1], cu[mt][nt][half_ * 2 + 1]);
                hp[nt * 4] = __floats2half2_rn(o0, o1);
            }
        }
    }
}

// ======================= GEMM2 (fp16, BK=64) =======================
#define G2_A_STG 18432
#define G2_B_OFF (3 * 18432)                  /* 55296 */
#define G2_B_STG 17408
#define G2_SMEM  (55296 + 3 * 17408)          /* 107520 */

__device__ __forceinline__ void g2_load_stage(uint32_t sb, int s, int c,
                                              const __half* __restrict__ W2h,
                                              int base, int m0, int n, int n0, int tid) {
    const int k0 = c * 64;
    const uint32_t aB = sb + s * G2_A_STG;
    #pragma unroll
    for (int q = 0; q < 4; q++) {               // 128 rows x 8 granules
        int id = q * 256 + tid, row = id >> 3, gq = id & 7;
        int rg = m0 + row; if (rg >= n) rg = n - 1;
        CP16(aB + row * 144 + gq * 16, g_hh + (size_t)(base + rg) * FF + k0 + gq * 8);
    }
    const uint32_t bB = sb + G2_B_OFF + s * G2_B_STG;
    #pragma unroll
    for (int q = 0; q < 4; q++) {               // 64 k-rows x 16 granules
        int id = q * 256 + tid, row = id >> 4, gq = id & 15;
        CP16(bB + row * 272 + gq * 16, W2h + (size_t)(k0 + row) * HD + n0 + gq * 8);
    }
    CP_COMMIT();
}

__global__ __launch_bounds__(256, 2) void gemm2_mma() {
    const int e = blockIdx.z;
    int n = 0, base = 0;
    #pragma unroll
    for (int i = 0; i < NE; i++) {
        int ci = g_counts[i];
        if (i < e) base += ci;
        if (i == e) n = ci;
    }
    const int m0 = blockIdx.y * 128;
    if (m0 >= n) return;
    const int n0 = blockIdx.x * 128;

    extern __shared__ char dynsmem[];
    const uint32_t sb = smem_u32(dynsmem);

    const int tid = threadIdx.x, wid = tid >> 5, lane = tid & 31;
    const int g = lane >> 2, tig = lane & 3;
    const int wm = wid >> 1, wn = wid & 1;

    const __half* __restrict__ W2h = g_w2h + (size_t)e * FF * HD;

    float cacc[2][8][4] = {};

    const uint32_t aAddr = sb + (wm * 32 + (lane & 15)) * 144 + (lane >> 4) * 16;
    const uint32_t bAddr = sb + G2_B_OFF + (lane & 15) * 272 + (lane >> 4) * 16 + wn * 128;

    uint32_t Af[2][2][4], Bf[2][4][4];

    g2_load_stage(sb, 0, 0, W2h, base, m0, n, n0, tid);
    g2_load_stage(sb, 1, 1, W2h, base, m0, n, n0, tid);
    g2_load_stage(sb, 2, 2, W2h, base, m0, n, n0, tid);
    CP_WAIT2();
    __syncthreads();
    ldmx4(Af[0][0], aAddr);
    ldmx4(Af[0][1], aAddr + 16 * 144);
    #pragma unroll
    for (int p = 0; p < 4; p++)
        ldmx4t(Bf[0][p], bAddr + p * 32);

    const int NC = FF / 64;   // 64 chunks
    for (int c = 0; c < NC; c++) {
        const int s = c % 3;
        const uint32_t aS = aAddr + s * G2_A_STG;
        const uint32_t bS = bAddr + s * G2_B_STG;

        #pragma unroll
        for (int ks = 0; ks < 4; ks++) {
            const int cur = ks & 1;
            if (ks < 3) {
                const int nxt = cur ^ 1;
                const uint32_t ao = aS + (ks + 1) * 32;
                const uint32_t bo = bS + (ks + 1) * 4352;
                ldmx4(Af[nxt][0], ao);
                ldmx4(Af[nxt][1], ao + 16 * 144);
                #pragma unroll
                for (int p = 0; p < 4; p++)
                    ldmx4t(Bf[nxt][p], bo + p * 32);
            }
            #pragma unroll
            for (int nt = 0; nt < 8; nt++) {
                const uint32_t* b = &Bf[cur][nt >> 1][(nt & 1) * 2];
                #pragma unroll
                for (int mt = 0; mt < 2; mt++)
                    mma16(cacc[mt][nt], Af[cur][mt], b);
            }
        }

        if (c + 1 < NC) {
            if (c + 2 < NC) { CP_WAIT1(); } else { CP_WAIT0(); }
            __syncthreads();
            const int s1 = (c + 1) % 3;
            const uint32_t aN = aAddr + s1 * G2_A_STG;
            const uint32_t bN = bAddr + s1 * G2_B_STG;
            ldmx4(Af[0][0], aN);
            ldmx4(Af[0][1], aN + 16 * 144);
            #pragma unroll
            for (int p = 0; p < 4; p++)
                ldmx4t(Bf[0][p], bN + p * 32);
            if (c + 3 < NC)
                g2_load_stage(sb, s, c + 3, W2h, base, m0, n, n0, tid);
        }
    }

    #pragma unroll
    for (int mt = 0; mt < 2; mt++) {
        #pragma unroll
        for (int half_ = 0; half_ < 2; half_++) {
            const int r = m0 + wm * 32 + mt * 16 + g + half_ * 8;
            if (r >= n) continue;
            float* yp = g_y + (size_t)(base + r) * HD + n0 + wn * 64 + 2 * tig;
            #pragma unroll
            for (int nt = 0; nt < 8; nt++) {
                float2 o;
                o.x = cacc[mt][nt][half_ * 2 + 0];
                o.y = cacc[mt][nt][half_ * 2 + 1];
                *(float2*)(yp + nt * 8) = o;
            }
        }
    }
}

// ---------------- combine ----------------
__global__ void combine_kernel(float* __restrict__ out) {
    __shared__ int sbase[NE];
    if (threadIdx.x == 0) {
        int b = 0;
        #pragma unroll
        for (int e = 0; e < NE; e++) { sbase[e] = b; b += g_counts[e]; }
    }
    __syncthreads();
    const int idx = blockIdx.x * blockDim.x + threadIdx.x;
    const int t = idx / (HD / 4);
    const int c4 = idx % (HD / 4);
    float4 acc = make_float4(0.f, 0.f, 0.f, 0.f);
    #pragma unroll
    for (int k = 0; k < TOPK; k++) {
        int e = g_sel_e[t * 2 + k];
        int s = g_sel_s[t * 2 + k];
        float w = g_sel_w[t * 2 + k];
        const float4 v = *(const float4*)(g_y + (size_t)(sbase[e] + s) * HD + c4 * 4);
        acc.x += w * v.x; acc.y += w * v.y; acc.z += w * v.z; acc.w += w * v.w;
    }
    *(float4*)(out + (size_t)t * HD + c4 * 4) = acc;
}

// ---------------- launcher ----------------
extern "C" void kernel_launch(void* const* d_in, const int* in_sizes, int n_in,
                              void* d_out, int out_size) {
    const float* x  = (const float*)d_in[0];
    const float* Wg = (const float*)d_in[1];
    const float* bg = (const float*)d_in[2];
    const float* W1 = (const float*)d_in[3];
    const float* W3 = (const float*)d_in[4];
    const float* W2 = (const float*)d_in[5];
    float* out = (float*)d_out;

    cudaFuncSetAttribute(gemm1_mma, cudaFuncAttributeMaxDynamicSharedMemorySize, G1_SMEM);
    cudaFuncSetAttribute(gemm2_mma, cudaFuncAttributeMaxDynamicSharedMemorySize, G2_SMEM);

    const int wN4 = NE * HD * FF / 4;

    // launch index 3 = gemm1 (ncu capture slot)
    zero_counts_kernel<<<1, 32>>>();                                          // 0
    routing_kernel<<<TOK, 256>>>(x, Wg, bg);                                  // 1 (+x convert)
    cvt_w13_kernel<<<(2 * wN4) / 256, 256>>>((const float4*)W1, (const float4*)W3); // 2
    gemm1_mma<<<dim3(FF / 64, TOK / 128, NE), 256, G1_SMEM>>>();              // 3
    cvt_w2_kernel<<<wN4 / 256, 256>>>((const float4*)W2);                     // 4
    gemm2_mma<<<dim3(HD / 128, TOK / 128, NE), 256, G2_SMEM>>>();             // 5
    combine_kernel<<<(TOK * (HD / 4)) / 256, 256>>>(out);                     // 6
}